// round 1
// baseline (speedup 1.0000x reference)
#include <cuda_runtime.h>
#include <math.h>

#define BB 2
#define SS 2048
#define DMODEL 1024
#define NH 16
#define NKV 4
#define DK 64

// Scratch (allocation-free rule: __device__ globals)
__device__ __align__(16) float g_Q[(size_t)BB * NH * SS * DK];      // [B,H,S,dk]
__device__ __align__(16) float g_ctx[(size_t)BB * SS * DMODEL];     // [B,S,H*dk]

// ---------------------------------------------------------------------------
// Tiled SGEMM: C = A[M,K] @ W[K,N] + bias, 64x64 tile, BK=16, 4x4 microtile.
// mode 0: plain row-major store to C
// mode 1: store to g_Q in [B,H,S,dk] layout (Q projection)
// mode 2: store to C in [B,KVH,S,dk] layout (K/V projection -> d_out regions)
// asrc 1: read A from g_ctx (final output projection)
// ---------------------------------------------------------------------------
__global__ __launch_bounds__(256, 2)
void gemm64(const float* __restrict__ A, const float* __restrict__ W,
            const float* __restrict__ bias, float* __restrict__ C,
            int M, int N, int K, int mode, int asrc)
{
    __shared__ __align__(16) float As[64 * 20];  // [m][k], stride 20 (pad)
    __shared__ __align__(16) float Bs[16 * 68];  // [k][n], stride 68 (pad)
    if (asrc) A = g_ctx;

    const int tid = threadIdx.x;
    const int tx = tid & 15, ty = tid >> 4;
    const int m0 = blockIdx.y << 6, n0 = blockIdx.x << 6;

    float acc[4][4] = {};

    for (int kb = 0; kb < K; kb += 16) {
        // Load A tile 64x16 (256 float4)
        {
            int r = tid >> 2, c4 = (tid & 3) << 2;
            float4 v = *(const float4*)(A + (size_t)(m0 + r) * K + kb + c4);
            As[r * 20 + c4 + 0] = v.x;
            As[r * 20 + c4 + 1] = v.y;
            As[r * 20 + c4 + 2] = v.z;
            As[r * 20 + c4 + 3] = v.w;
        }
        // Load B tile 16x64 (256 float4)
        {
            int kk = tid >> 4, c4 = (tid & 15) << 2;
            *(float4*)(Bs + kk * 68 + c4) =
                *(const float4*)(W + (size_t)(kb + kk) * N + n0 + c4);
        }
        __syncthreads();

#pragma unroll
        for (int k = 0; k < 16; k++) {
            float a[4];
#pragma unroll
            for (int i = 0; i < 4; i++) a[i] = As[(4 * ty + i) * 20 + k];
            float4 bv = *(float4*)(Bs + k * 68 + 4 * tx);
#pragma unroll
            for (int i = 0; i < 4; i++) {
                acc[i][0] += a[i] * bv.x;
                acc[i][1] += a[i] * bv.y;
                acc[i][2] += a[i] * bv.z;
                acc[i][3] += a[i] * bv.w;
            }
        }
        __syncthreads();
    }

#pragma unroll
    for (int i = 0; i < 4; i++) {
        int m = m0 + 4 * ty + i;
        int b = m >> 11, srow = m & 2047;
#pragma unroll
        for (int j = 0; j < 4; j++) {
            int n = n0 + 4 * tx + j;
            float v = acc[i][j] + bias[n];
            if (mode == 0) {
                C[(size_t)m * N + n] = v;
            } else if (mode == 1) {
                int h = n >> 6, d = n & 63;
                g_Q[(((size_t)b * NH + h) * SS + srow) * DK + d] = v;
            } else {
                int kv = n >> 6, d = n & 63;
                C[(((size_t)b * NKV + kv) * SS + srow) * DK + d] = v;
            }
        }
    }
}

// ---------------------------------------------------------------------------
// Flash attention, fp32, non-causal. One block = 64 query rows of one (b,h).
// Q tile stays resident; loop over 32 key tiles of 64. Online softmax with
// per-row stats reduced across the 16 tx lanes via shuffles.
// K tile stored d-major (KP[d][c]); P tile overwrites the K buffer.
// Static smem = 3 * 64*64 * 4B = 48 KB exactly.
// ---------------------------------------------------------------------------
__global__ __launch_bounds__(256, 2)
void attn64(const float* __restrict__ Kg, const float* __restrict__ Vg)
{
    __shared__ __align__(16) float Qs[64 * 64];  // [r][d]
    __shared__ __align__(16) float KP[64 * 64];  // K: [d][c]  /  P: [r][c]
    __shared__ __align__(16) float Vs[64 * 64];  // [c][d]

    const int tid = threadIdx.x;
    const int tx = tid & 15, ty = tid >> 4;
    const int bh = blockIdx.y;                 // 0..31
    const int b = bh >> 4, h = bh & 15;
    const int kv = h >> 2;                     // h / G
    const int q0 = blockIdx.x << 6;

    const float* Qp = g_Q + (((size_t)b * NH + h) * SS + q0) * DK;
    const float* Kp = Kg + ((size_t)b * NKV + kv) * SS * DK;
    const float* Vp = Vg + ((size_t)b * NKV + kv) * SS * DK;

    // Load Q tile [64 rows][64 dims]
    for (int i = tid; i < 64 * 16; i += 256) {
        int r = i >> 4, c4 = (i & 15) << 2;
        *(float4*)(Qs + r * 64 + c4) = *(const float4*)(Qp + (size_t)r * DK + c4);
    }

    float mrow[4], lrow[4], O[4][4];
#pragma unroll
    for (int i = 0; i < 4; i++) {
        mrow[i] = -1e30f;
        lrow[i] = 0.f;
#pragma unroll
        for (int j = 0; j < 4; j++) O[i][j] = 0.f;
    }

    for (int kt = 0; kt < SS; kt += 64) {
        // Load K tile transposed: KP[d][c]
        for (int i = tid; i < 4096; i += 256) {
            int c = i >> 6, d = i & 63;
            KP[d * 64 + c] = Kp[(size_t)(kt + c) * DK + d];
        }
        // Load V tile natural: Vs[c][d]
        for (int i = tid; i < 64 * 16; i += 256) {
            int c = i >> 4, d4 = (i & 15) << 2;
            *(float4*)(Vs + c * 64 + d4) =
                *(const float4*)(Vp + (size_t)(kt + c) * DK + d4);
        }
        __syncthreads();

        // S = Q K^T  (4x4 microtile per thread)
        float sc[4][4] = {};
#pragma unroll 16
        for (int d = 0; d < 64; d++) {
            float a[4];
#pragma unroll
            for (int i = 0; i < 4; i++) a[i] = Qs[(4 * ty + i) * 64 + d];
            float4 bv = *(float4*)(KP + d * 64 + 4 * tx);
#pragma unroll
            for (int i = 0; i < 4; i++) {
                sc[i][0] += a[i] * bv.x;
                sc[i][1] += a[i] * bv.y;
                sc[i][2] += a[i] * bv.z;
                sc[i][3] += a[i] * bv.w;
            }
        }

        // Online softmax (scale 1/sqrt(64) = 0.125)
        float p[4][4];
#pragma unroll
        for (int i = 0; i < 4; i++) {
            float mx = -1e30f;
#pragma unroll
            for (int j = 0; j < 4; j++) {
                sc[i][j] *= 0.125f;
                mx = fmaxf(mx, sc[i][j]);
            }
#pragma unroll
            for (int o = 8; o; o >>= 1)
                mx = fmaxf(mx, __shfl_xor_sync(0xffffffffu, mx, o));
            float mn = fmaxf(mrow[i], mx);
            float fc = __expf(mrow[i] - mn);
            mrow[i] = mn;
            float rs = 0.f;
#pragma unroll
            for (int j = 0; j < 4; j++) {
                p[i][j] = __expf(sc[i][j] - mn);
                rs += p[i][j];
            }
#pragma unroll
            for (int o = 8; o; o >>= 1)
                rs += __shfl_xor_sync(0xffffffffu, rs, o);
            lrow[i] = lrow[i] * fc + rs;
#pragma unroll
            for (int j = 0; j < 4; j++) O[i][j] *= fc;
        }

        __syncthreads();  // all K reads done -> safe to overwrite as P
#pragma unroll
        for (int i = 0; i < 4; i++)
            *(float4*)(KP + (4 * ty + i) * 64 + 4 * tx) =
                make_float4(p[i][0], p[i][1], p[i][2], p[i][3]);
        __syncthreads();

        // O += P V
#pragma unroll 16
        for (int c = 0; c < 64; c++) {
            float a[4];
#pragma unroll
            for (int i = 0; i < 4; i++) a[i] = KP[(4 * ty + i) * 64 + c];
            float4 bv = *(float4*)(Vs + c * 64 + 4 * tx);
#pragma unroll
            for (int i = 0; i < 4; i++) {
                O[i][0] += a[i] * bv.x;
                O[i][1] += a[i] * bv.y;
                O[i][2] += a[i] * bv.z;
                O[i][3] += a[i] * bv.w;
            }
        }
        __syncthreads();  // before next tile's loads overwrite KP/Vs
    }

    // Normalize and write ctx in [B,S,H*dk] layout
#pragma unroll
    for (int i = 0; i < 4; i++) {
        float inv = 1.f / lrow[i];
        float4 o4 = make_float4(O[i][0] * inv, O[i][1] * inv,
                                O[i][2] * inv, O[i][3] * inv);
        size_t row = (size_t)b * SS + q0 + 4 * ty + i;
        *(float4*)(g_ctx + row * DMODEL + h * DK + 4 * tx) = o4;
    }
}

// ---------------------------------------------------------------------------
extern "C" void kernel_launch(void* const* d_in, const int* in_sizes, int n_in,
                              void* d_out, int out_size)
{
    const float* query    = (const float*)d_in[0];
    const float* key_in   = (const float*)d_in[1];
    const float* value_in = (const float*)d_in[2];
    const float* Wq = (const float*)d_in[3];
    const float* bq = (const float*)d_in[4];
    const float* Wk = (const float*)d_in[5];
    const float* bk = (const float*)d_in[6];
    const float* Wv = (const float*)d_in[7];
    const float* bv = (const float*)d_in[8];
    const float* Wo = (const float*)d_in[9];
    const float* bo = (const float*)d_in[10];

    float* out  = (float*)d_out;
    float* outO = out;                                    // [B,S,DM]
    float* outK = out + (size_t)BB * SS * DMODEL;         // [B,KVH,S,dk]
    float* outV = outK + (size_t)BB * NKV * SS * DK;      // [B,KVH,S,dk]

    const int M = BB * SS;  // 4096

    // K, V projections -> directly into d_out in [B,KVH,S,dk] layout
    gemm64<<<dim3((NKV * DK) / 64, M / 64), 256>>>(
        key_in, Wk, bk, outK, M, NKV * DK, DMODEL, 2, 0);
    gemm64<<<dim3((NKV * DK) / 64, M / 64), 256>>>(
        value_in, Wv, bv, outV, M, NKV * DK, DMODEL, 2, 0);
    // Q projection -> g_Q in [B,H,S,dk] layout
    gemm64<<<dim3(DMODEL / 64, M / 64), 256>>>(
        query, Wq, bq, out, M, DMODEL, DMODEL, 1, 0);
    // Attention -> g_ctx
    attn64<<<dim3(SS / 64, BB * NH), 256>>>(outK, outV);
    // Output projection: g_ctx @ Wo + bo -> outO
    gemm64<<<dim3(DMODEL / 64, M / 64), 256>>>(
        out, Wo, bo, outO, M, DMODEL, DMODEL, 0, 1);
}

// round 3
// speedup vs baseline: 3.4887x; 3.4887x over previous
#include <cuda_runtime.h>
#include <cuda_bf16.h>
#include <cstdint>
#include <math.h>

#define BB 2
#define SS 2048
#define DMODEL 1024
#define NH 16
#define NKV 4
#define DK 64

// ---------------------------------------------------------------------------
// Helpers: ldmatrix / mma.sync / cp.async (all valid on base sm_103 PTX)
// ---------------------------------------------------------------------------
__device__ __forceinline__ uint32_t smem_u32(const void* p) {
    uint32_t a;
    asm("{ .reg .u64 t; cvta.to.shared.u64 t, %1; cvt.u32.u64 %0, t; }"
        : "=r"(a) : "l"(p));
    return a;
}
__device__ __forceinline__ void ldsm4(uint32_t& r0, uint32_t& r1, uint32_t& r2,
                                      uint32_t& r3, uint32_t addr) {
    asm volatile("ldmatrix.sync.aligned.m8n8.x4.shared.b16 {%0,%1,%2,%3}, [%4];"
                 : "=r"(r0), "=r"(r1), "=r"(r2), "=r"(r3) : "r"(addr));
}
__device__ __forceinline__ void ldsm2(uint32_t& r0, uint32_t& r1, uint32_t addr) {
    asm volatile("ldmatrix.sync.aligned.m8n8.x2.shared.b16 {%0,%1}, [%2];"
                 : "=r"(r0), "=r"(r1) : "r"(addr));
}
__device__ __forceinline__ void mma_bf16(float* c, const uint32_t* a, const uint32_t* b) {
    asm volatile(
        "mma.sync.aligned.m16n8k16.row.col.f32.bf16.bf16.f32 "
        "{%0,%1,%2,%3}, {%4,%5,%6,%7}, {%8,%9}, {%0,%1,%2,%3};"
        : "+f"(c[0]), "+f"(c[1]), "+f"(c[2]), "+f"(c[3])
        : "r"(a[0]), "r"(a[1]), "r"(a[2]), "r"(a[3]), "r"(b[0]), "r"(b[1]));
}
#define CP16(dst, src) \
    asm volatile("cp.async.cg.shared.global [%0], [%1], 16;" :: "r"(dst), "l"(src))
#define CP_COMMIT() asm volatile("cp.async.commit_group;" ::: "memory")
#define CP_WAIT(n)  asm volatile("cp.async.wait_group %0;" :: "n"(n) : "memory")

__device__ __forceinline__ uint32_t packbf(float lo, float hi) {
    uint32_t r;
    asm("cvt.rn.bf16x2.f32 %0, %1, %2;" : "=r"(r) : "f"(hi), "f"(lo));
    return r;
}
__device__ __forceinline__ float bfrt(float x) {   // bf16 round-trip
    return __bfloat162float(__float2bfloat16_rn(x));
}

// ---------------------------------------------------------------------------
// Scratch device globals
// ---------------------------------------------------------------------------
__device__ __align__(16) float g_ctx[(size_t)BB * SS * DMODEL];
__device__ __align__(16) __nv_bfloat16 g_Xh[(size_t)BB * SS * DMODEL];
__device__ __align__(16) __nv_bfloat16 g_Xl[(size_t)BB * SS * DMODEL];
__device__ __align__(16) __nv_bfloat16 g_Wh[(size_t)DMODEL * DMODEL];   // [N][K]
__device__ __align__(16) __nv_bfloat16 g_Wl[(size_t)DMODEL * DMODEL];
__device__ __align__(16) __nv_bfloat16 g_Qh[(size_t)BB * NH * SS * DK];  // [B,H,S,dk]
__device__ __align__(16) __nv_bfloat16 g_Ql[(size_t)BB * NH * SS * DK];
__device__ __align__(16) __nv_bfloat16 g_Kh[(size_t)BB * NKV * SS * DK]; // [B,KV,S,dk]
__device__ __align__(16) __nv_bfloat16 g_Kl[(size_t)BB * NKV * SS * DK];
__device__ __align__(16) __nv_bfloat16 g_Vth[(size_t)BB * NKV * DK * SS]; // [B,KV,dk,S]
__device__ __align__(16) __nv_bfloat16 g_Vtl[(size_t)BB * NKV * DK * SS];

// ---------------------------------------------------------------------------
// splitA: fp32 -> bf16 hi/lo, same layout
// ---------------------------------------------------------------------------
__global__ void splitA(const float* __restrict__ X, int asrc) {
    if (asrc) X = g_ctx;
    int i = (blockIdx.x * 256 + threadIdx.x) * 4;
    float4 v = *(const float4*)(X + i);
    uint2 h, l;
    h.x = packbf(v.x, v.y); h.y = packbf(v.z, v.w);
    l.x = packbf(v.x - bfrt(v.x), v.y - bfrt(v.y));
    l.y = packbf(v.z - bfrt(v.z), v.w - bfrt(v.w));
    *(uint2*)(g_Xh + i) = h;
    *(uint2*)(g_Xl + i) = l;
}

// splitW: W [K,N] fp32 -> g_Wh/g_Wl [N,K] bf16
__global__ void splitW(const float* __restrict__ W, int K, int N) {
    __shared__ float t[32][33];
    int tx = threadIdx.x, ty = threadIdx.y;
    int n0 = blockIdx.x * 32, k0 = blockIdx.y * 32;
#pragma unroll
    for (int i = 0; i < 4; i++)
        t[ty + 8 * i][tx] = W[(size_t)(k0 + ty + 8 * i) * N + n0 + tx];
    __syncthreads();
#pragma unroll
    for (int i = 0; i < 4; i++) {
        int row = ty + 8 * i;
        float v = t[tx][row];
        g_Wh[(size_t)(n0 + row) * K + k0 + tx] = __float2bfloat16_rn(v);
        g_Wl[(size_t)(n0 + row) * K + k0 + tx] = __float2bfloat16_rn(v - bfrt(v));
    }
}

// ---------------------------------------------------------------------------
// HMMA split-bf16 GEMM. CTA tile 128x64, K-chunk 64, double-buffered cp.async.
// Warp w computes rows 16w..16w+15, all 64 cols (8 n8-frags).
// Smem stage layout (bytes): Ah 0..18432, Al ..36864, Bh ..46080, Bl ..55296
// modes: 0=fp32 C[m][1024]; 1=Q->g_Qh/l; 2=K->C[B,KV,S,dk]+g_Kh/l; 3=V->C+g_Vth/l
// ---------------------------------------------------------------------------
#define STG 55296
#define GEMM_SMEM (2 * STG)

__global__ __launch_bounds__(256)
void gemm_mma(const float* __restrict__ bias, float* __restrict__ C, int mode)
{
    extern __shared__ char sm[];
    const uint32_t sb = smem_u32(sm);
    const int tid = threadIdx.x;
    const int wid = tid >> 5, lane = tid & 31;
    const int m0 = blockIdx.y << 7, n0 = blockIdx.x << 6;

    auto load_chunk = [&](int c, int s) {
        const int kc0 = c * 64;
        const uint32_t st = sb + s * STG;
#pragma unroll
        for (int j = 0; j < 4; j++) {                   // A: 128 rows x 8 groups
            int idx = tid + j * 256;
            int r = idx >> 3, kg = idx & 7;
            uint32_t d = st + r * 144 + kg * 16;
            size_t src = (size_t)(m0 + r) * DMODEL + kc0 + kg * 8;
            CP16(d,         g_Xh + src);
            CP16(d + 18432, g_Xl + src);
        }
#pragma unroll
        for (int j = 0; j < 2; j++) {                   // B: 64 rows x 8 groups
            int idx = tid + j * 256;
            int r = idx >> 3, kg = idx & 7;
            uint32_t d = st + 36864 + r * 144 + kg * 16;
            size_t src = (size_t)(n0 + r) * DMODEL + kc0 + kg * 8;
            CP16(d,        g_Wh + src);
            CP16(d + 9216, g_Wl + src);
        }
    };

    float acc[8][4] = {};

    load_chunk(0, 0);
    CP_COMMIT();

    for (int c = 0; c < 16; c++) {
        if (c < 15) { load_chunk(c + 1, (c + 1) & 1); CP_COMMIT(); CP_WAIT(1); }
        else        { CP_WAIT(0); }
        __syncthreads();

        const uint32_t st = sb + (c & 1) * STG;
#pragma unroll
        for (int ks = 0; ks < 4; ks++) {
            uint32_t ah[4], al[4];
            uint32_t aaddr = st + (wid * 16 + (lane & 15)) * 144
                           + (ks * 16 + (lane >> 4) * 8) * 2;
            ldsm4(ah[0], ah[1], ah[2], ah[3], aaddr);
            ldsm4(al[0], al[1], al[2], al[3], aaddr + 18432);
#pragma unroll
            for (int nf = 0; nf < 8; nf++) {
                uint32_t bh[2], bl[2];
                uint32_t baddr = st + 36864 + (nf * 8 + (lane & 7)) * 144
                               + (ks * 16 + ((lane >> 3) & 1) * 8) * 2;
                ldsm2(bh[0], bh[1], baddr);
                ldsm2(bl[0], bl[1], baddr + 9216);
                mma_bf16(acc[nf], ah, bh);
                mma_bf16(acc[nf], al, bh);
                mma_bf16(acc[nf], ah, bl);
            }
        }
        __syncthreads();
    }

    // Epilogue: stage in smem [128][68] fp32 with bias added
    float* Ds = (float*)sm;
    {
        int r0 = wid * 16 + (lane >> 2);
#pragma unroll
        for (int nf = 0; nf < 8; nf++) {
            int cb = nf * 8 + (lane & 3) * 2;
            float b0 = bias[n0 + cb], b1 = bias[n0 + cb + 1];
            Ds[r0 * 68 + cb]           = acc[nf][0] + b0;
            Ds[r0 * 68 + cb + 1]       = acc[nf][1] + b1;
            Ds[(r0 + 8) * 68 + cb]     = acc[nf][2] + b0;
            Ds[(r0 + 8) * 68 + cb + 1] = acc[nf][3] + b1;
        }
    }
    __syncthreads();

#pragma unroll
    for (int j = 0; j < 8; j++) {
        int idx = tid + j * 256;               // 2048 float4
        int r = idx >> 4, c4 = (idx & 15) << 2;
        float4 v = *(float4*)(Ds + r * 68 + c4);
        int m = m0 + r, b = m >> 11, srow = m & 2047;
        if (mode == 0) {
            *(float4*)(C + (size_t)m * DMODEL + n0 + c4) = v;
        } else {
            uint2 h, l;
            h.x = packbf(v.x, v.y); h.y = packbf(v.z, v.w);
            l.x = packbf(v.x - bfrt(v.x), v.y - bfrt(v.y));
            l.y = packbf(v.z - bfrt(v.z), v.w - bfrt(v.w));
            if (mode == 1) {
                int h_ = n0 >> 6;
                size_t off = (((size_t)b * NH + h_) * SS + srow) * DK + c4;
                *(uint2*)(g_Qh + off) = h;
                *(uint2*)(g_Ql + off) = l;
            } else {
                int kv = n0 >> 6;
                size_t off = (((size_t)b * NKV + kv) * SS + srow) * DK + c4;
                *(float4*)(C + off) = v;
                if (mode == 2) {
                    *(uint2*)(g_Kh + off) = h;
                    *(uint2*)(g_Kl + off) = l;
                }
            }
        }
    }

    if (mode == 3) {   // V: transposed bf16 copies [B,KV,dk,S]
        int kv = n0 >> 6;
#pragma unroll
        for (int j = 0; j < 32; j++) {
            int idx = tid + j * 256;           // 8192 elements
            int d = idx >> 7, sl = idx & 127;
            float v = Ds[sl * 68 + d];
            int m = m0 + sl, b = m >> 11, srow = m & 2047;
            size_t off = (((size_t)b * NKV + kv) * DK + d) * SS + srow;
            g_Vth[off] = __float2bfloat16_rn(v);
            g_Vtl[off] = __float2bfloat16_rn(v - bfrt(v));
        }
    }
}

// ---------------------------------------------------------------------------
// Flash attention on HMMA. CTA = 128 q-rows of one (b,h). 8 warps, warp owns
// 16 complete rows -> warp-local softmax. K/V tiles (64 keys) double-buffered.
// Smem: Q (hi 0 / lo 18432) 36864B; KV stages at 36864 + s*36864:
//   Kh +0, Kl +9216, Vh +18432, Vl +27648  (each 64 rows x 144B)
// ---------------------------------------------------------------------------
#define ATT_SMEM (36864 + 2 * 36864)

__global__ __launch_bounds__(256)
void attn_mma(void)
{
    extern __shared__ char sm[];
    const uint32_t sb = smem_u32(sm);
    const int tid = threadIdx.x;
    const int wid = tid >> 5, lane = tid & 31;
    const int bh = blockIdx.y;
    const int b = bh >> 4, h = bh & 15, kv = h >> 2;
    const int q0 = blockIdx.x << 7;

    const size_t qbase = (((size_t)b * NH + h) * SS + q0) * DK;
    const size_t kbase = ((size_t)b * NKV + kv) * SS * DK;
    const size_t vbase = ((size_t)b * NKV + kv) * DK * SS;

    auto load_kv = [&](int kt, int s) {
        const uint32_t st = sb + 36864 + s * 36864;
#pragma unroll
        for (int j = 0; j < 2; j++) {
            int idx = tid + j * 256;
            int r = idx >> 3, kg = idx & 7;
            uint32_t d = st + r * 144 + kg * 16;
            size_t ksrc = kbase + (size_t)(kt * 64 + r) * DK + kg * 8;
            CP16(d,        g_Kh + ksrc);
            CP16(d + 9216, g_Kl + ksrc);
            size_t vsrc = vbase + (size_t)r * SS + kt * 64 + kg * 8;
            CP16(d + 18432, g_Vth + vsrc);
            CP16(d + 27648, g_Vtl + vsrc);
        }
    };

    // Q load (group 0 together with kv tile 0)
#pragma unroll
    for (int j = 0; j < 4; j++) {
        int idx = tid + j * 256;
        int r = idx >> 3, kg = idx & 7;
        uint32_t d = sb + r * 144 + kg * 16;
        size_t src = qbase + (size_t)r * DK + kg * 8;
        CP16(d,         g_Qh + src);
        CP16(d + 18432, g_Ql + src);
    }
    load_kv(0, 0);
    CP_COMMIT();

    float O[8][4] = {};
    float mprev0 = -1e30f, mprev1 = -1e30f, lsum0 = 0.f, lsum1 = 0.f;

    for (int kt = 0; kt < 32; kt++) {
        if (kt < 31) { load_kv(kt + 1, (kt + 1) & 1); CP_COMMIT(); CP_WAIT(1); }
        else         { CP_WAIT(0); }
        __syncthreads();

        const uint32_t st = sb + 36864 + (kt & 1) * 36864;

        // S = Q K^T
        float S[8][4] = {};
#pragma unroll
        for (int ks = 0; ks < 4; ks++) {
            uint32_t qh[4], ql[4];
            uint32_t aaddr = sb + (wid * 16 + (lane & 15)) * 144
                           + (ks * 16 + (lane >> 4) * 8) * 2;
            ldsm4(qh[0], qh[1], qh[2], qh[3], aaddr);
            ldsm4(ql[0], ql[1], ql[2], ql[3], aaddr + 18432);
#pragma unroll
            for (int nf = 0; nf < 8; nf++) {
                uint32_t kh[2], kl[2];
                uint32_t baddr = st + (nf * 8 + (lane & 7)) * 144
                               + (ks * 16 + ((lane >> 3) & 1) * 8) * 2;
                ldsm2(kh[0], kh[1], baddr);
                ldsm2(kl[0], kl[1], baddr + 9216);
                mma_bf16(S[nf], qh, kh);
                mma_bf16(S[nf], ql, kh);
                mma_bf16(S[nf], qh, kl);
            }
        }

        // Online softmax (scale 1/8)
        float mx0 = -1e30f, mx1 = -1e30f;
#pragma unroll
        for (int nf = 0; nf < 8; nf++) {
#pragma unroll
            for (int j = 0; j < 4; j++) S[nf][j] *= 0.125f;
            mx0 = fmaxf(mx0, fmaxf(S[nf][0], S[nf][1]));
            mx1 = fmaxf(mx1, fmaxf(S[nf][2], S[nf][3]));
        }
        mx0 = fmaxf(mx0, __shfl_xor_sync(0xffffffffu, mx0, 1));
        mx0 = fmaxf(mx0, __shfl_xor_sync(0xffffffffu, mx0, 2));
        mx1 = fmaxf(mx1, __shfl_xor_sync(0xffffffffu, mx1, 1));
        mx1 = fmaxf(mx1, __shfl_xor_sync(0xffffffffu, mx1, 2));
        float mn0 = fmaxf(mprev0, mx0), mn1 = fmaxf(mprev1, mx1);
        float fac0 = __expf(mprev0 - mn0), fac1 = __expf(mprev1 - mn1);
        mprev0 = mn0; mprev1 = mn1;

        uint32_t ph[8][2], pl[8][2];
        float ps0 = 0.f, ps1 = 0.f;
#pragma unroll
        for (int nf = 0; nf < 8; nf++) {
            float p00 = __expf(S[nf][0] - mn0), p01 = __expf(S[nf][1] - mn0);
            float p10 = __expf(S[nf][2] - mn1), p11 = __expf(S[nf][3] - mn1);
            ps0 += p00 + p01; ps1 += p10 + p11;
            ph[nf][0] = packbf(p00, p01);
            ph[nf][1] = packbf(p10, p11);
            pl[nf][0] = packbf(p00 - bfrt(p00), p01 - bfrt(p01));
            pl[nf][1] = packbf(p10 - bfrt(p10), p11 - bfrt(p11));
        }
        ps0 += __shfl_xor_sync(0xffffffffu, ps0, 1);
        ps0 += __shfl_xor_sync(0xffffffffu, ps0, 2);
        ps1 += __shfl_xor_sync(0xffffffffu, ps1, 1);
        ps1 += __shfl_xor_sync(0xffffffffu, ps1, 2);
        lsum0 = lsum0 * fac0 + ps0;
        lsum1 = lsum1 * fac1 + ps1;
#pragma unroll
        for (int nd = 0; nd < 8; nd++) {
            O[nd][0] *= fac0; O[nd][1] *= fac0;
            O[nd][2] *= fac1; O[nd][3] *= fac1;
        }

        // O += P V
#pragma unroll
        for (int ks = 0; ks < 4; ks++) {
            uint32_t a_h[4] = { ph[2*ks][0], ph[2*ks][1], ph[2*ks+1][0], ph[2*ks+1][1] };
            uint32_t a_l[4] = { pl[2*ks][0], pl[2*ks][1], pl[2*ks+1][0], pl[2*ks+1][1] };
#pragma unroll
            for (int nd = 0; nd < 8; nd++) {
                uint32_t vh[2], vl[2];
                uint32_t vaddr = st + 18432 + (nd * 8 + (lane & 7)) * 144
                               + (ks * 16 + ((lane >> 3) & 1) * 8) * 2;
                ldsm2(vh[0], vh[1], vaddr);
                ldsm2(vl[0], vl[1], vaddr + 9216);
                mma_bf16(O[nd], a_h, vh);
                mma_bf16(O[nd], a_l, vh);
                mma_bf16(O[nd], a_h, vl);
            }
        }
        __syncthreads();
    }

    // Normalize + stage through smem (overwrites Q area), coalesced ctx write
    float inv0 = 1.f / lsum0, inv1 = 1.f / lsum1;
    float* Os = (float*)sm;
    {
        int r0 = wid * 16 + (lane >> 2);
#pragma unroll
        for (int nd = 0; nd < 8; nd++) {
            int cb = nd * 8 + (lane & 3) * 2;
            Os[r0 * 68 + cb]           = O[nd][0] * inv0;
            Os[r0 * 68 + cb + 1]       = O[nd][1] * inv0;
            Os[(r0 + 8) * 68 + cb]     = O[nd][2] * inv1;
            Os[(r0 + 8) * 68 + cb + 1] = O[nd][3] * inv1;
        }
    }
    __syncthreads();
#pragma unroll
    for (int j = 0; j < 8; j++) {
        int idx = tid + j * 256;
        int r = idx >> 4, c4 = (idx & 15) << 2;
        float4 v = *(float4*)(Os + r * 68 + c4);
        *(float4*)(g_ctx + ((size_t)b * SS + q0 + r) * DMODEL + h * DK + c4) = v;
    }
}

// ---------------------------------------------------------------------------
extern "C" void kernel_launch(void* const* d_in, const int* in_sizes, int n_in,
                              void* d_out, int out_size)
{
    const float* query    = (const float*)d_in[0];
    const float* key_in   = (const float*)d_in[1];
    const float* value_in = (const float*)d_in[2];
    const float* Wq = (const float*)d_in[3];
    const float* bq = (const float*)d_in[4];
    const float* Wk = (const float*)d_in[5];
    const float* bk = (const float*)d_in[6];
    const float* Wv = (const float*)d_in[7];
    const float* bv = (const float*)d_in[8];
    const float* Wo = (const float*)d_in[9];
    const float* bo = (const float*)d_in[10];

    float* out  = (float*)d_out;
    float* outO = out;
    float* outK = out + (size_t)BB * SS * DMODEL;
    float* outV = outK + (size_t)BB * NKV * SS * DK;

    static int attr_done = 0;
    cudaFuncSetAttribute(gemm_mma, cudaFuncAttributeMaxDynamicSharedMemorySize, GEMM_SMEM);
    cudaFuncSetAttribute(attn_mma, cudaFuncAttributeMaxDynamicSharedMemorySize, ATT_SMEM);
    (void)attr_done;

    const int M = BB * SS;                    // 4096
    const int sA = M * DMODEL / 4 / 256;      // splitA blocks
    dim3 tb(32, 8);

    // K projection
    splitW<<<dim3(NKV * DK / 32, DMODEL / 32), tb>>>(Wk, DMODEL, NKV * DK);
    splitA<<<sA, 256>>>(key_in, 0);
    gemm_mma<<<dim3(NKV * DK / 64, M / 128), 256, GEMM_SMEM>>>(bk, outK, 2);

    // V projection
    splitW<<<dim3(NKV * DK / 32, DMODEL / 32), tb>>>(Wv, DMODEL, NKV * DK);
    splitA<<<sA, 256>>>(value_in, 0);
    gemm_mma<<<dim3(NKV * DK / 64, M / 128), 256, GEMM_SMEM>>>(bv, outV, 3);

    // Q projection
    splitW<<<dim3(DMODEL / 32, DMODEL / 32), tb>>>(Wq, DMODEL, DMODEL);
    splitA<<<sA, 256>>>(query, 0);
    gemm_mma<<<dim3(DMODEL / 64, M / 128), 256, GEMM_SMEM>>>(bq, out, 1);

    // Attention
    attn_mma<<<dim3(SS / 128, BB * NH), 256, ATT_SMEM>>>();

    // Output projection
    splitW<<<dim3(DMODEL / 32, DMODEL / 32), tb>>>(Wo, DMODEL, DMODEL);
    splitA<<<sA, 256>>>(nullptr, 1);
    gemm_mma<<<dim3(DMODEL / 64, M / 128), 256, GEMM_SMEM>>>(bo, outO, 0);
}

// round 4
// speedup vs baseline: 3.6339x; 1.0416x over previous
#include <cuda_runtime.h>
#include <cuda_bf16.h>
#include <cstdint>
#include <math.h>

#define BB 2
#define SS 2048
#define DMODEL 1024
#define NH 16
#define NKV 4
#define DK 64

// ---------------------------------------------------------------------------
// Helpers
// ---------------------------------------------------------------------------
__device__ __forceinline__ uint32_t smem_u32(const void* p) {
    uint32_t a;
    asm("{ .reg .u64 t; cvta.to.shared.u64 t, %1; cvt.u32.u64 %0, t; }"
        : "=r"(a) : "l"(p));
    return a;
}
__device__ __forceinline__ void ldsm4(uint32_t& r0, uint32_t& r1, uint32_t& r2,
                                      uint32_t& r3, uint32_t addr) {
    asm volatile("ldmatrix.sync.aligned.m8n8.x4.shared.b16 {%0,%1,%2,%3}, [%4];"
                 : "=r"(r0), "=r"(r1), "=r"(r2), "=r"(r3) : "r"(addr));
}
__device__ __forceinline__ void ldsm2(uint32_t& r0, uint32_t& r1, uint32_t addr) {
    asm volatile("ldmatrix.sync.aligned.m8n8.x2.shared.b16 {%0,%1}, [%2];"
                 : "=r"(r0), "=r"(r1) : "r"(addr));
}
__device__ __forceinline__ void mma_bf16(float* c, const uint32_t* a, const uint32_t* b) {
    asm volatile(
        "mma.sync.aligned.m16n8k16.row.col.f32.bf16.bf16.f32 "
        "{%0,%1,%2,%3}, {%4,%5,%6,%7}, {%8,%9}, {%0,%1,%2,%3};"
        : "+f"(c[0]), "+f"(c[1]), "+f"(c[2]), "+f"(c[3])
        : "r"(a[0]), "r"(a[1]), "r"(a[2]), "r"(a[3]), "r"(b[0]), "r"(b[1]));
}
#define CP16(dst, src) \
    asm volatile("cp.async.cg.shared.global [%0], [%1], 16;" :: "r"(dst), "l"(src))
#define CP_COMMIT() asm volatile("cp.async.commit_group;" ::: "memory")
#define CP_WAIT(n)  asm volatile("cp.async.wait_group %0;" :: "n"(n) : "memory")

__device__ __forceinline__ uint32_t packbf(float lo, float hi) {
    uint32_t r;
    asm("cvt.rn.bf16x2.f32 %0, %1, %2;" : "=r"(r) : "f"(hi), "f"(lo));
    return r;
}
__device__ __forceinline__ float bfrt(float x) {
    return __bfloat162float(__float2bfloat16_rn(x));
}

// ---------------------------------------------------------------------------
// Scratch globals
// ---------------------------------------------------------------------------
#define XSLOT ((size_t)4194304)            // 4096*1024 elems per input slot
__device__ __align__(16) __nv_bfloat16 g_Xh[3 * XSLOT];  // q,k,v activations
__device__ __align__(16) __nv_bfloat16 g_Xl[3 * XSLOT];
#define WSLOT ((size_t)1048576)
__device__ __align__(16) __nv_bfloat16 g_Wh[4 * WSLOT];  // Wq,Wk,Wv,Wo [N][K]
__device__ __align__(16) __nv_bfloat16 g_Wl[4 * WSLOT];
__device__ __align__(16) __nv_bfloat16 g_CXh[(size_t)BB * SS * DMODEL];  // ctx
__device__ __align__(16) __nv_bfloat16 g_CXl[(size_t)BB * SS * DMODEL];
__device__ __align__(16) __nv_bfloat16 g_Qh[(size_t)BB * NH * SS * DK];
__device__ __align__(16) __nv_bfloat16 g_Ql[(size_t)BB * NH * SS * DK];
__device__ __align__(16) __nv_bfloat16 g_Kh[(size_t)BB * NKV * SS * DK];
__device__ __align__(16) __nv_bfloat16 g_Kl[(size_t)BB * NKV * SS * DK];
__device__ __align__(16) __nv_bfloat16 g_Vth[(size_t)BB * NKV * DK * SS]; // [B,KV,dk,S]
__device__ __align__(16) __nv_bfloat16 g_Vtl[(size_t)BB * NKV * DK * SS];

// ---------------------------------------------------------------------------
// Fused activation split: q,k,v -> slots 0,1,2 of g_Xh/g_Xl
// ---------------------------------------------------------------------------
__global__ void splitA_all(const float* __restrict__ q, const float* __restrict__ k,
                           const float* __restrict__ v) {
    size_t g = ((size_t)blockIdx.x * 256 + threadIdx.x) * 4;
    size_t slot = g >> 22, off = g & (XSLOT - 1);
    const float* X = slot == 0 ? q : (slot == 1 ? k : v);
    float4 vv = *(const float4*)(X + off);
    uint2 h, l;
    h.x = packbf(vv.x, vv.y); h.y = packbf(vv.z, vv.w);
    l.x = packbf(vv.x - bfrt(vv.x), vv.y - bfrt(vv.y));
    l.y = packbf(vv.z - bfrt(vv.z), vv.w - bfrt(vv.w));
    *(uint2*)(g_Xh + g) = h;
    *(uint2*)(g_Xl + g) = l;
}

// Fused weight transpose+split: 4 weights -> slots of g_Wh/g_Wl [N][1024]
__global__ void splitW_all(const float* __restrict__ Wq, const float* __restrict__ Wk,
                           const float* __restrict__ Wv, const float* __restrict__ Wo) {
    __shared__ float t[32][33];
    int id = blockIdx.x;
    const float* W; int slot, nb, N;
    if (id < 32)      { W = Wq; slot = 0; nb = id;      N = 1024; }
    else if (id < 40) { W = Wk; slot = 1; nb = id - 32; N = 256;  }
    else if (id < 48) { W = Wv; slot = 2; nb = id - 40; N = 256;  }
    else              { W = Wo; slot = 3; nb = id - 48; N = 1024; }
    int tx = threadIdx.x, ty = threadIdx.y;
    int n0 = nb * 32, k0 = blockIdx.y * 32;
#pragma unroll
    for (int i = 0; i < 4; i++)
        t[ty + 8 * i][tx] = W[(size_t)(k0 + ty + 8 * i) * N + n0 + tx];
    __syncthreads();
    __nv_bfloat16* Wh = g_Wh + slot * WSLOT;
    __nv_bfloat16* Wl = g_Wl + slot * WSLOT;
#pragma unroll
    for (int i = 0; i < 4; i++) {
        int row = ty + 8 * i;
        float v = t[tx][row];
        Wh[(size_t)(n0 + row) * DMODEL + k0 + tx] = __float2bfloat16_rn(v);
        Wl[(size_t)(n0 + row) * DMODEL + k0 + tx] = __float2bfloat16_rn(v - bfrt(v));
    }
}

// ---------------------------------------------------------------------------
// HMMA split-bf16 GEMM. CTA 128x64, K-chunk 64, 2-buffer cp.async.
// 2-D warp grid 4x2, warp tile 32x32 (2 m-frags x 4 n-frags).
// modes: 0=fp32 C[m][1024]; 1=Q->g_Qh/l; 2=K->C[B,KV,S,dk]+g_Kh/l; 3=V->C+g_Vth/l
// ---------------------------------------------------------------------------
#define STG 55296
#define GEMM_SMEM (2 * STG)

__global__ __launch_bounds__(256)
void gemm_mma(const __nv_bfloat16* __restrict__ Ah_g, const __nv_bfloat16* __restrict__ Al_g,
              const __nv_bfloat16* __restrict__ Wh_g, const __nv_bfloat16* __restrict__ Wl_g,
              const float* __restrict__ bias, float* __restrict__ C, int mode)
{
    extern __shared__ char sm[];
    const uint32_t sb = smem_u32(sm);
    const int tid = threadIdx.x;
    const int wid = tid >> 5, lane = tid & 31;
    const int wm = wid & 3, wn = wid >> 2;
    const int m0 = blockIdx.y << 7, n0 = blockIdx.x << 6;

    auto load_chunk = [&](int c, int s) {
        const int kc0 = c * 64;
        const uint32_t st = sb + s * STG;
#pragma unroll
        for (int j = 0; j < 4; j++) {
            int idx = tid + j * 256;
            int r = idx >> 3, kg = idx & 7;
            uint32_t d = st + r * 144 + kg * 16;
            size_t src = (size_t)(m0 + r) * DMODEL + kc0 + kg * 8;
            CP16(d,         Ah_g + src);
            CP16(d + 18432, Al_g + src);
        }
#pragma unroll
        for (int j = 0; j < 2; j++) {
            int idx = tid + j * 256;
            int r = idx >> 3, kg = idx & 7;
            uint32_t d = st + 36864 + r * 144 + kg * 16;
            size_t src = (size_t)(n0 + r) * DMODEL + kc0 + kg * 8;
            CP16(d,        Wh_g + src);
            CP16(d + 9216, Wl_g + src);
        }
    };

    float acc[2][4][4] = {};

    load_chunk(0, 0);
    CP_COMMIT();

    for (int c = 0; c < 16; c++) {
        if (c < 15) { load_chunk(c + 1, (c + 1) & 1); CP_COMMIT(); CP_WAIT(1); }
        else        { CP_WAIT(0); }
        __syncthreads();

        const uint32_t st = sb + (c & 1) * STG;
#pragma unroll
        for (int ks = 0; ks < 4; ks++) {
            uint32_t ah[2][4], al[2][4];
#pragma unroll
            for (int mf = 0; mf < 2; mf++) {
                uint32_t aaddr = st + (wm * 32 + mf * 16 + (lane & 15)) * 144
                               + (ks * 16 + (lane >> 4) * 8) * 2;
                ldsm4(ah[mf][0], ah[mf][1], ah[mf][2], ah[mf][3], aaddr);
                ldsm4(al[mf][0], al[mf][1], al[mf][2], al[mf][3], aaddr + 18432);
            }
#pragma unroll
            for (int nf = 0; nf < 4; nf++) {
                uint32_t bh[2], bl[2];
                uint32_t baddr = st + 36864 + (wn * 32 + nf * 8 + (lane & 7)) * 144
                               + (ks * 16 + ((lane >> 3) & 1) * 8) * 2;
                ldsm2(bh[0], bh[1], baddr);
                ldsm2(bl[0], bl[1], baddr + 9216);
#pragma unroll
                for (int mf = 0; mf < 2; mf++) {
                    mma_bf16(acc[mf][nf], ah[mf], bh);
                    mma_bf16(acc[mf][nf], al[mf], bh);
                    mma_bf16(acc[mf][nf], ah[mf], bl);
                }
            }
        }
        __syncthreads();
    }

    // Epilogue: stage in smem [128][68] fp32 with bias
    float* Ds = (float*)sm;
#pragma unroll
    for (int mf = 0; mf < 2; mf++) {
        int r0 = wm * 32 + mf * 16 + (lane >> 2);
#pragma unroll
        for (int nf = 0; nf < 4; nf++) {
            int cb = wn * 32 + nf * 8 + (lane & 3) * 2;
            float b0 = bias[n0 + cb], b1 = bias[n0 + cb + 1];
            Ds[r0 * 68 + cb]           = acc[mf][nf][0] + b0;
            Ds[r0 * 68 + cb + 1]       = acc[mf][nf][1] + b1;
            Ds[(r0 + 8) * 68 + cb]     = acc[mf][nf][2] + b0;
            Ds[(r0 + 8) * 68 + cb + 1] = acc[mf][nf][3] + b1;
        }
    }
    __syncthreads();

#pragma unroll
    for (int j = 0; j < 8; j++) {
        int idx = tid + j * 256;
        int r = idx >> 4, c4 = (idx & 15) << 2;
        float4 v = *(float4*)(Ds + r * 68 + c4);
        int m = m0 + r, b = m >> 11, srow = m & 2047;
        if (mode == 0) {
            *(float4*)(C + (size_t)m * DMODEL + n0 + c4) = v;
        } else {
            uint2 h, l;
            h.x = packbf(v.x, v.y); h.y = packbf(v.z, v.w);
            l.x = packbf(v.x - bfrt(v.x), v.y - bfrt(v.y));
            l.y = packbf(v.z - bfrt(v.z), v.w - bfrt(v.w));
            if (mode == 1) {
                int h_ = n0 >> 6;
                size_t off = (((size_t)b * NH + h_) * SS + srow) * DK + c4;
                *(uint2*)(g_Qh + off) = h;
                *(uint2*)(g_Ql + off) = l;
            } else {
                int kv = n0 >> 6;
                size_t off = (((size_t)b * NKV + kv) * SS + srow) * DK + c4;
                *(float4*)(C + off) = v;
                if (mode == 2) {
                    *(uint2*)(g_Kh + off) = h;
                    *(uint2*)(g_Kl + off) = l;
                }
            }
        }
    }

    if (mode == 3) {
        int kv = n0 >> 6;
#pragma unroll
        for (int j = 0; j < 32; j++) {
            int idx = tid + j * 256;
            int d = idx >> 7, sl = idx & 127;
            float v = Ds[sl * 68 + d];
            int m = m0 + sl, b = m >> 11, srow = m & 2047;
            size_t off = (((size_t)b * NKV + kv) * DK + d) * SS + srow;
            g_Vth[off] = __float2bfloat16_rn(v);
            g_Vtl[off] = __float2bfloat16_rn(v - bfrt(v));
        }
    }
}

// ---------------------------------------------------------------------------
// Flash attention on HMMA (R3 design). Epilogue now writes bf16 hi/lo ctx.
// ---------------------------------------------------------------------------
#define ATT_SMEM (36864 + 2 * 36864)

__global__ __launch_bounds__(256)
void attn_mma(void)
{
    extern __shared__ char sm[];
    const uint32_t sb = smem_u32(sm);
    const int tid = threadIdx.x;
    const int wid = tid >> 5, lane = tid & 31;
    const int bh = blockIdx.y;
    const int b = bh >> 4, h = bh & 15, kv = h >> 2;
    const int q0 = blockIdx.x << 7;

    const size_t qbase = (((size_t)b * NH + h) * SS + q0) * DK;
    const size_t kbase = ((size_t)b * NKV + kv) * SS * DK;
    const size_t vbase = ((size_t)b * NKV + kv) * DK * SS;

    auto load_kv = [&](int kt, int s) {
        const uint32_t st = sb + 36864 + s * 36864;
#pragma unroll
        for (int j = 0; j < 2; j++) {
            int idx = tid + j * 256;
            int r = idx >> 3, kg = idx & 7;
            uint32_t d = st + r * 144 + kg * 16;
            size_t ksrc = kbase + (size_t)(kt * 64 + r) * DK + kg * 8;
            CP16(d,        g_Kh + ksrc);
            CP16(d + 9216, g_Kl + ksrc);
            size_t vsrc = vbase + (size_t)r * SS + kt * 64 + kg * 8;
            CP16(d + 18432, g_Vth + vsrc);
            CP16(d + 27648, g_Vtl + vsrc);
        }
    };

#pragma unroll
    for (int j = 0; j < 4; j++) {
        int idx = tid + j * 256;
        int r = idx >> 3, kg = idx & 7;
        uint32_t d = sb + r * 144 + kg * 16;
        size_t src = qbase + (size_t)r * DK + kg * 8;
        CP16(d,         g_Qh + src);
        CP16(d + 18432, g_Ql + src);
    }
    load_kv(0, 0);
    CP_COMMIT();

    float O[8][4] = {};
    float mprev0 = -1e30f, mprev1 = -1e30f, lsum0 = 0.f, lsum1 = 0.f;

    for (int kt = 0; kt < 32; kt++) {
        if (kt < 31) { load_kv(kt + 1, (kt + 1) & 1); CP_COMMIT(); CP_WAIT(1); }
        else         { CP_WAIT(0); }
        __syncthreads();

        const uint32_t st = sb + 36864 + (kt & 1) * 36864;

        float S[8][4] = {};
#pragma unroll
        for (int ks = 0; ks < 4; ks++) {
            uint32_t qh[4], ql[4];
            uint32_t aaddr = sb + (wid * 16 + (lane & 15)) * 144
                           + (ks * 16 + (lane >> 4) * 8) * 2;
            ldsm4(qh[0], qh[1], qh[2], qh[3], aaddr);
            ldsm4(ql[0], ql[1], ql[2], ql[3], aaddr + 18432);
#pragma unroll
            for (int nf = 0; nf < 8; nf++) {
                uint32_t kh[2], kl[2];
                uint32_t baddr = st + (nf * 8 + (lane & 7)) * 144
                               + (ks * 16 + ((lane >> 3) & 1) * 8) * 2;
                ldsm2(kh[0], kh[1], baddr);
                ldsm2(kl[0], kl[1], baddr + 9216);
                mma_bf16(S[nf], qh, kh);
                mma_bf16(S[nf], ql, kh);
                mma_bf16(S[nf], qh, kl);
            }
        }

        float mx0 = -1e30f, mx1 = -1e30f;
#pragma unroll
        for (int nf = 0; nf < 8; nf++) {
#pragma unroll
            for (int j = 0; j < 4; j++) S[nf][j] *= 0.125f;
            mx0 = fmaxf(mx0, fmaxf(S[nf][0], S[nf][1]));
            mx1 = fmaxf(mx1, fmaxf(S[nf][2], S[nf][3]));
        }
        mx0 = fmaxf(mx0, __shfl_xor_sync(0xffffffffu, mx0, 1));
        mx0 = fmaxf(mx0, __shfl_xor_sync(0xffffffffu, mx0, 2));
        mx1 = fmaxf(mx1, __shfl_xor_sync(0xffffffffu, mx1, 1));
        mx1 = fmaxf(mx1, __shfl_xor_sync(0xffffffffu, mx1, 2));
        float mn0 = fmaxf(mprev0, mx0), mn1 = fmaxf(mprev1, mx1);
        float fac0 = __expf(mprev0 - mn0), fac1 = __expf(mprev1 - mn1);
        mprev0 = mn0; mprev1 = mn1;

        uint32_t ph[8][2], pl[8][2];
        float ps0 = 0.f, ps1 = 0.f;
#pragma unroll
        for (int nf = 0; nf < 8; nf++) {
            float p00 = __expf(S[nf][0] - mn0), p01 = __expf(S[nf][1] - mn0);
            float p10 = __expf(S[nf][2] - mn1), p11 = __expf(S[nf][3] - mn1);
            ps0 += p00 + p01; ps1 += p10 + p11;
            ph[nf][0] = packbf(p00, p01);
            ph[nf][1] = packbf(p10, p11);
            pl[nf][0] = packbf(p00 - bfrt(p00), p01 - bfrt(p01));
            pl[nf][1] = packbf(p10 - bfrt(p10), p11 - bfrt(p11));
        }
        ps0 += __shfl_xor_sync(0xffffffffu, ps0, 1);
        ps0 += __shfl_xor_sync(0xffffffffu, ps0, 2);
        ps1 += __shfl_xor_sync(0xffffffffu, ps1, 1);
        ps1 += __shfl_xor_sync(0xffffffffu, ps1, 2);
        lsum0 = lsum0 * fac0 + ps0;
        lsum1 = lsum1 * fac1 + ps1;
#pragma unroll
        for (int nd = 0; nd < 8; nd++) {
            O[nd][0] *= fac0; O[nd][1] *= fac0;
            O[nd][2] *= fac1; O[nd][3] *= fac1;
        }

#pragma unroll
        for (int ks = 0; ks < 4; ks++) {
            uint32_t a_h[4] = { ph[2*ks][0], ph[2*ks][1], ph[2*ks+1][0], ph[2*ks+1][1] };
            uint32_t a_l[4] = { pl[2*ks][0], pl[2*ks][1], pl[2*ks+1][0], pl[2*ks+1][1] };
#pragma unroll
            for (int nd = 0; nd < 8; nd++) {
                uint32_t vh[2], vl[2];
                uint32_t vaddr = st + 18432 + (nd * 8 + (lane & 7)) * 144
                               + (ks * 16 + ((lane >> 3) & 1) * 8) * 2;
                ldsm2(vh[0], vh[1], vaddr);
                ldsm2(vl[0], vl[1], vaddr + 9216);
                mma_bf16(O[nd], a_h, vh);
                mma_bf16(O[nd], a_l, vh);
                mma_bf16(O[nd], a_h, vl);
            }
        }
        __syncthreads();
    }

    float inv0 = 1.f / lsum0, inv1 = 1.f / lsum1;
    float* Os = (float*)sm;
    {
        int r0 = wid * 16 + (lane >> 2);
#pragma unroll
        for (int nd = 0; nd < 8; nd++) {
            int cb = nd * 8 + (lane & 3) * 2;
            Os[r0 * 68 + cb]           = O[nd][0] * inv0;
            Os[r0 * 68 + cb + 1]       = O[nd][1] * inv0;
            Os[(r0 + 8) * 68 + cb]     = O[nd][2] * inv1;
            Os[(r0 + 8) * 68 + cb + 1] = O[nd][3] * inv1;
        }
    }
    __syncthreads();
#pragma unroll
    for (int j = 0; j < 8; j++) {
        int idx = tid + j * 256;
        int r = idx >> 4, c4 = (idx & 15) << 2;
        float4 v = *(float4*)(Os + r * 68 + c4);
        uint2 hh, ll;
        hh.x = packbf(v.x, v.y); hh.y = packbf(v.z, v.w);
        ll.x = packbf(v.x - bfrt(v.x), v.y - bfrt(v.y));
        ll.y = packbf(v.z - bfrt(v.z), v.w - bfrt(v.w));
        size_t off = ((size_t)b * SS + q0 + r) * DMODEL + h * DK + c4;
        *(uint2*)(g_CXh + off) = hh;
        *(uint2*)(g_CXl + off) = ll;
    }
}

// ---------------------------------------------------------------------------
extern "C" void kernel_launch(void* const* d_in, const int* in_sizes, int n_in,
                              void* d_out, int out_size)
{
    const float* query    = (const float*)d_in[0];
    const float* key_in   = (const float*)d_in[1];
    const float* value_in = (const float*)d_in[2];
    const float* Wq = (const float*)d_in[3];
    const float* bq = (const float*)d_in[4];
    const float* Wk = (const float*)d_in[5];
    const float* bk = (const float*)d_in[6];
    const float* Wv = (const float*)d_in[7];
    const float* bv = (const float*)d_in[8];
    const float* Wo = (const float*)d_in[9];
    const float* bo = (const float*)d_in[10];

    float* out  = (float*)d_out;
    float* outO = out;
    float* outK = out + (size_t)BB * SS * DMODEL;
    float* outV = outK + (size_t)BB * NKV * SS * DK;

    // One-time host-side resources (no device work, deterministic graphs)
    static cudaStream_t s1 = nullptr, s2 = nullptr;
    static cudaEvent_t evRoot, evW, evAW, e1, e2;
    static __nv_bfloat16 *Xh, *Xl, *Wh, *Wl, *CXh, *CXl;
    if (!s1) {
        cudaStreamCreateWithFlags(&s1, cudaStreamNonBlocking);
        cudaStreamCreateWithFlags(&s2, cudaStreamNonBlocking);
        cudaEventCreateWithFlags(&evRoot, cudaEventDisableTiming);
        cudaEventCreateWithFlags(&evW,    cudaEventDisableTiming);
        cudaEventCreateWithFlags(&evAW,   cudaEventDisableTiming);
        cudaEventCreateWithFlags(&e1,     cudaEventDisableTiming);
        cudaEventCreateWithFlags(&e2,     cudaEventDisableTiming);
        cudaGetSymbolAddress((void**)&Xh,  g_Xh);
        cudaGetSymbolAddress((void**)&Xl,  g_Xl);
        cudaGetSymbolAddress((void**)&Wh,  g_Wh);
        cudaGetSymbolAddress((void**)&Wl,  g_Wl);
        cudaGetSymbolAddress((void**)&CXh, g_CXh);
        cudaGetSymbolAddress((void**)&CXl, g_CXl);
        cudaFuncSetAttribute(gemm_mma, cudaFuncAttributeMaxDynamicSharedMemorySize, GEMM_SMEM);
        cudaFuncSetAttribute(attn_mma, cudaFuncAttributeMaxDynamicSharedMemorySize, ATT_SMEM);
    }

    const int M = BB * SS;   // 4096

    // Fork: stream0 = splitA, s1 = splitW
    cudaEventRecord(evRoot, 0);
    cudaStreamWaitEvent(s1, evRoot, 0);
    cudaStreamWaitEvent(s2, evRoot, 0);

    splitA_all<<<3 * XSLOT / 1024, 256>>>(query, key_in, value_in);
    splitW_all<<<dim3(80, 32), dim3(32, 8), 0, s1>>>(Wq, Wk, Wv, Wo);
    cudaEventRecord(evW, s1);
    cudaStreamWaitEvent(0, evW, 0);
    cudaEventRecord(evAW, 0);
    cudaStreamWaitEvent(s1, evAW, 0);
    cudaStreamWaitEvent(s2, evAW, 0);

    // Q on stream0, K on s1, V on s2 — concurrent
    gemm_mma<<<dim3(16, M / 128), 256, GEMM_SMEM>>>(
        Xh, Xl, Wh, Wl, bq, out, 1);
    gemm_mma<<<dim3(4, M / 128), 256, GEMM_SMEM, s1>>>(
        Xh + XSLOT, Xl + XSLOT, Wh + WSLOT, Wl + WSLOT, bk, outK, 2);
    gemm_mma<<<dim3(4, M / 128), 256, GEMM_SMEM, s2>>>(
        Xh + 2 * XSLOT, Xl + 2 * XSLOT, Wh + 2 * WSLOT, Wl + 2 * WSLOT, bv, outV, 3);
    cudaEventRecord(e1, s1);
    cudaEventRecord(e2, s2);
    cudaStreamWaitEvent(0, e1, 0);
    cudaStreamWaitEvent(0, e2, 0);

    // Attention (writes bf16 hi/lo ctx directly)
    attn_mma<<<dim3(SS / 128, BB * NH), 256, ATT_SMEM>>>();

    // Output projection
    gemm_mma<<<dim3(16, M / 128), 256, GEMM_SMEM>>>(
        CXh, CXl, Wh + 3 * WSLOT, Wl + 3 * WSLOT, bo, outO, 0);
}

// round 5
// speedup vs baseline: 4.0292x; 1.1088x over previous
#include <cuda_runtime.h>
#include <cuda_bf16.h>
#include <cstdint>
#include <math.h>

#define BB 2
#define SS 2048
#define DMODEL 1024
#define NH 16
#define NKV 4
#define DK 64

// ---------------------------------------------------------------------------
// Helpers
// ---------------------------------------------------------------------------
__device__ __forceinline__ uint32_t smem_u32(const void* p) {
    uint32_t a;
    asm("{ .reg .u64 t; cvta.to.shared.u64 t, %1; cvt.u32.u64 %0, t; }"
        : "=r"(a) : "l"(p));
    return a;
}
__device__ __forceinline__ void ldsm4(uint32_t& r0, uint32_t& r1, uint32_t& r2,
                                      uint32_t& r3, uint32_t addr) {
    asm volatile("ldmatrix.sync.aligned.m8n8.x4.shared.b16 {%0,%1,%2,%3}, [%4];"
                 : "=r"(r0), "=r"(r1), "=r"(r2), "=r"(r3) : "r"(addr));
}
__device__ __forceinline__ void ldsm2(uint32_t& r0, uint32_t& r1, uint32_t addr) {
    asm volatile("ldmatrix.sync.aligned.m8n8.x2.shared.b16 {%0,%1}, [%2];"
                 : "=r"(r0), "=r"(r1) : "r"(addr));
}
__device__ __forceinline__ void mma_bf16(float* c, const uint32_t* a, const uint32_t* b) {
    asm volatile(
        "mma.sync.aligned.m16n8k16.row.col.f32.bf16.bf16.f32 "
        "{%0,%1,%2,%3}, {%4,%5,%6,%7}, {%8,%9}, {%0,%1,%2,%3};"
        : "+f"(c[0]), "+f"(c[1]), "+f"(c[2]), "+f"(c[3])
        : "r"(a[0]), "r"(a[1]), "r"(a[2]), "r"(a[3]), "r"(b[0]), "r"(b[1]));
}
#define CP16(dst, src) \
    asm volatile("cp.async.cg.shared.global [%0], [%1], 16;" :: "r"(dst), "l"(src))
#define CP_COMMIT() asm volatile("cp.async.commit_group;" ::: "memory")
#define CP_WAIT(n)  asm volatile("cp.async.wait_group %0;" :: "n"(n) : "memory")
#define SW(o) ((o) ^ (((o) >> 3) & 0x70))   // XOR swizzle for 128B rows

__device__ __forceinline__ uint32_t packbf(float lo, float hi) {
    uint32_t r;
    asm("cvt.rn.bf16x2.f32 %0, %1, %2;" : "=r"(r) : "f"(hi), "f"(lo));
    return r;
}
__device__ __forceinline__ float bfrt(float x) {
    return __bfloat162float(__float2bfloat16_rn(x));
}

// ---------------------------------------------------------------------------
// Scratch globals
// ---------------------------------------------------------------------------
#define XSLOT ((size_t)4194304)
__device__ __align__(16) __nv_bfloat16 g_Xh[3 * XSLOT];
__device__ __align__(16) __nv_bfloat16 g_Xl[3 * XSLOT];
#define WSLOT ((size_t)1048576)
__device__ __align__(16) __nv_bfloat16 g_Wh[4 * WSLOT];
__device__ __align__(16) __nv_bfloat16 g_Wl[4 * WSLOT];
__device__ __align__(16) __nv_bfloat16 g_CXh[(size_t)BB * SS * DMODEL];
__device__ __align__(16) __nv_bfloat16 g_CXl[(size_t)BB * SS * DMODEL];
__device__ __align__(16) __nv_bfloat16 g_Qh[(size_t)BB * NH * SS * DK];
__device__ __align__(16) __nv_bfloat16 g_Ql[(size_t)BB * NH * SS * DK];
__device__ __align__(16) __nv_bfloat16 g_Kh[(size_t)BB * NKV * SS * DK];
__device__ __align__(16) __nv_bfloat16 g_Kl[(size_t)BB * NKV * SS * DK];
__device__ __align__(16) __nv_bfloat16 g_Vth[(size_t)BB * NKV * DK * SS];
__device__ __align__(16) __nv_bfloat16 g_Vtl[(size_t)BB * NKV * DK * SS];

// ---------------------------------------------------------------------------
__global__ void splitA_all(const float* __restrict__ q, const float* __restrict__ k,
                           const float* __restrict__ v) {
    size_t g = ((size_t)blockIdx.x * 256 + threadIdx.x) * 4;
    size_t slot = g >> 22, off = g & (XSLOT - 1);
    const float* X = slot == 0 ? q : (slot == 1 ? k : v);
    float4 vv = *(const float4*)(X + off);
    uint2 h, l;
    h.x = packbf(vv.x, vv.y); h.y = packbf(vv.z, vv.w);
    l.x = packbf(vv.x - bfrt(vv.x), vv.y - bfrt(vv.y));
    l.y = packbf(vv.z - bfrt(vv.z), vv.w - bfrt(vv.w));
    *(uint2*)(g_Xh + g) = h;
    *(uint2*)(g_Xl + g) = l;
}

__global__ void splitW_all(const float* __restrict__ Wq, const float* __restrict__ Wk,
                           const float* __restrict__ Wv, const float* __restrict__ Wo) {
    __shared__ float t[32][33];
    int id = blockIdx.x;
    const float* W; int slot, nb, N;
    if (id < 32)      { W = Wq; slot = 0; nb = id;      N = 1024; }
    else if (id < 40) { W = Wk; slot = 1; nb = id - 32; N = 256;  }
    else if (id < 48) { W = Wv; slot = 2; nb = id - 40; N = 256;  }
    else              { W = Wo; slot = 3; nb = id - 48; N = 1024; }
    int tx = threadIdx.x, ty = threadIdx.y;
    int n0 = nb * 32, k0 = blockIdx.y * 32;
#pragma unroll
    for (int i = 0; i < 4; i++)
        t[ty + 8 * i][tx] = W[(size_t)(k0 + ty + 8 * i) * N + n0 + tx];
    __syncthreads();
    __nv_bfloat16* Wh = g_Wh + slot * WSLOT;
    __nv_bfloat16* Wl = g_Wl + slot * WSLOT;
#pragma unroll
    for (int i = 0; i < 4; i++) {
        int row = ty + 8 * i;
        float v = t[tx][row];
        Wh[(size_t)(n0 + row) * DMODEL + k0 + tx] = __float2bfloat16_rn(v);
        Wl[(size_t)(n0 + row) * DMODEL + k0 + tx] = __float2bfloat16_rn(v - bfrt(v));
    }
}

// ---------------------------------------------------------------------------
// HMMA split-bf16 GEMM. CTA 128x64, K-chunk 64, 2-buffer cp.async, swizzled
// 128B rows. Stage: Ah 0 (16K), Al 16K, Bh 32K (8K), Bl 40K. STG=48K.
// ---------------------------------------------------------------------------
#define STG 49152
#define GEMM_SMEM (2 * STG)

__global__ __launch_bounds__(256)
void gemm_mma(const __nv_bfloat16* __restrict__ Ah_g, const __nv_bfloat16* __restrict__ Al_g,
              const __nv_bfloat16* __restrict__ Wh_g, const __nv_bfloat16* __restrict__ Wl_g,
              const float* __restrict__ bias, float* __restrict__ C, int mode)
{
    extern __shared__ char sm[];
    const uint32_t sb = smem_u32(sm);
    const int tid = threadIdx.x;
    const int wid = tid >> 5, lane = tid & 31;
    const int wm = wid & 3, wn = wid >> 2;
    const int m0 = blockIdx.y << 7, n0 = blockIdx.x << 6;

    auto load_chunk = [&](int c, int s) {
        const int kc0 = c * 64;
        const uint32_t st = sb + s * STG;
#pragma unroll
        for (int j = 0; j < 4; j++) {
            int idx = tid + j * 256;
            int r = idx >> 3, kg = idx & 7;
            uint32_t off = SW((uint32_t)(r * 128 + kg * 16));
            size_t src = (size_t)(m0 + r) * DMODEL + kc0 + kg * 8;
            CP16(st + off,         Ah_g + src);
            CP16(st + 16384 + off, Al_g + src);
        }
#pragma unroll
        for (int j = 0; j < 2; j++) {
            int idx = tid + j * 256;
            int r = idx >> 3, kg = idx & 7;
            uint32_t off = SW((uint32_t)(r * 128 + kg * 16));
            size_t src = (size_t)(n0 + r) * DMODEL + kc0 + kg * 8;
            CP16(st + 32768 + off, Wh_g + src);
            CP16(st + 40960 + off, Wl_g + src);
        }
    };

    float acc[2][4][4] = {};

    load_chunk(0, 0);
    CP_COMMIT();

    for (int c = 0; c < 16; c++) {
        if (c < 15) { load_chunk(c + 1, (c + 1) & 1); CP_COMMIT(); CP_WAIT(1); }
        else        { CP_WAIT(0); }
        __syncthreads();

        const uint32_t st = sb + (c & 1) * STG;
#pragma unroll
        for (int ks = 0; ks < 4; ks++) {
            uint32_t ah[2][4], al[2][4];
#pragma unroll
            for (int mf = 0; mf < 2; mf++) {
                uint32_t ao = SW((uint32_t)((wm * 32 + mf * 16 + (lane & 15)) * 128
                                 + ks * 32 + (lane >> 4) * 16));
                ldsm4(ah[mf][0], ah[mf][1], ah[mf][2], ah[mf][3], st + ao);
                ldsm4(al[mf][0], al[mf][1], al[mf][2], al[mf][3], st + 16384 + ao);
            }
#pragma unroll
            for (int nf = 0; nf < 4; nf++) {
                uint32_t bh[2], bl[2];
                uint32_t bo = SW((uint32_t)((wn * 32 + nf * 8 + (lane & 7)) * 128
                                 + ks * 32 + ((lane >> 3) & 1) * 16));
                ldsm2(bh[0], bh[1], st + 32768 + bo);
                ldsm2(bl[0], bl[1], st + 40960 + bo);
#pragma unroll
                for (int mf = 0; mf < 2; mf++) {
                    mma_bf16(acc[mf][nf], ah[mf], bh);
                    mma_bf16(acc[mf][nf], al[mf], bh);
                    mma_bf16(acc[mf][nf], ah[mf], bl);
                }
            }
        }
        __syncthreads();
    }

    float* Ds = (float*)sm;
#pragma unroll
    for (int mf = 0; mf < 2; mf++) {
        int r0 = wm * 32 + mf * 16 + (lane >> 2);
#pragma unroll
        for (int nf = 0; nf < 4; nf++) {
            int cb = wn * 32 + nf * 8 + (lane & 3) * 2;
            float b0 = bias[n0 + cb], b1 = bias[n0 + cb + 1];
            Ds[r0 * 68 + cb]           = acc[mf][nf][0] + b0;
            Ds[r0 * 68 + cb + 1]       = acc[mf][nf][1] + b1;
            Ds[(r0 + 8) * 68 + cb]     = acc[mf][nf][2] + b0;
            Ds[(r0 + 8) * 68 + cb + 1] = acc[mf][nf][3] + b1;
        }
    }
    __syncthreads();

#pragma unroll
    for (int j = 0; j < 8; j++) {
        int idx = tid + j * 256;
        int r = idx >> 4, c4 = (idx & 15) << 2;
        float4 v = *(float4*)(Ds + r * 68 + c4);
        int m = m0 + r, b = m >> 11, srow = m & 2047;
        if (mode == 0) {
            *(float4*)(C + (size_t)m * DMODEL + n0 + c4) = v;
        } else {
            uint2 h, l;
            h.x = packbf(v.x, v.y); h.y = packbf(v.z, v.w);
            l.x = packbf(v.x - bfrt(v.x), v.y - bfrt(v.y));
            l.y = packbf(v.z - bfrt(v.z), v.w - bfrt(v.w));
            if (mode == 1) {
                int h_ = n0 >> 6;
                size_t off = (((size_t)b * NH + h_) * SS + srow) * DK + c4;
                *(uint2*)(g_Qh + off) = h;
                *(uint2*)(g_Ql + off) = l;
            } else {
                int kv = n0 >> 6;
                size_t off = (((size_t)b * NKV + kv) * SS + srow) * DK + c4;
                *(float4*)(C + off) = v;
                if (mode == 2) {
                    *(uint2*)(g_Kh + off) = h;
                    *(uint2*)(g_Kl + off) = l;
                }
            }
        }
    }

    if (mode == 3) {
        int kv = n0 >> 6;
#pragma unroll
        for (int j = 0; j < 32; j++) {
            int idx = tid + j * 256;
            int d = idx >> 7, sl = idx & 127;
            float v = Ds[sl * 68 + d];
            int m = m0 + sl, b = m >> 11, srow = m & 2047;
            size_t off = (((size_t)b * NKV + kv) * DK + d) * SS + srow;
            g_Vth[off] = __float2bfloat16_rn(v);
            g_Vtl[off] = __float2bfloat16_rn(v - bfrt(v));
        }
    }
}

// ---------------------------------------------------------------------------
// Flash attention. Smem: Qh 0 (16K), Ql 16K; KV stages at 32K + s*32K:
//   Kh +0 (8K), Kl +8K, Vh +16K, Vl +24K.  Total 96KB -> 2 CTAs/SM.
// ---------------------------------------------------------------------------
#define ATT_STG 32768
#define ATT_SMEM (32768 + 2 * ATT_STG)

__global__ __launch_bounds__(256)
void attn_mma(void)
{
    extern __shared__ char sm[];
    const uint32_t sb = smem_u32(sm);
    const int tid = threadIdx.x;
    const int wid = tid >> 5, lane = tid & 31;
    const int bh = blockIdx.y;
    const int b = bh >> 4, h = bh & 15, kv = h >> 2;
    const int q0 = blockIdx.x << 7;

    const size_t qbase = (((size_t)b * NH + h) * SS + q0) * DK;
    const size_t kbase = ((size_t)b * NKV + kv) * SS * DK;
    const size_t vbase = ((size_t)b * NKV + kv) * DK * SS;

    auto load_kv = [&](int kt, int s) {
        const uint32_t st = sb + 32768 + s * ATT_STG;
#pragma unroll
        for (int j = 0; j < 2; j++) {
            int idx = tid + j * 256;
            int r = idx >> 3, kg = idx & 7;
            uint32_t off = SW((uint32_t)(r * 128 + kg * 16));
            size_t ksrc = kbase + (size_t)(kt * 64 + r) * DK + kg * 8;
            CP16(st + off,        g_Kh + ksrc);
            CP16(st + 8192 + off, g_Kl + ksrc);
            size_t vsrc = vbase + (size_t)r * SS + kt * 64 + kg * 8;
            CP16(st + 16384 + off, g_Vth + vsrc);
            CP16(st + 24576 + off, g_Vtl + vsrc);
        }
    };

#pragma unroll
    for (int j = 0; j < 4; j++) {
        int idx = tid + j * 256;
        int r = idx >> 3, kg = idx & 7;
        uint32_t off = SW((uint32_t)(r * 128 + kg * 16));
        size_t src = qbase + (size_t)r * DK + kg * 8;
        CP16(sb + off,         g_Qh + src);
        CP16(sb + 16384 + off, g_Ql + src);
    }
    load_kv(0, 0);
    CP_COMMIT();

    float O[8][4] = {};
    float mprev0 = -1e30f, mprev1 = -1e30f, lsum0 = 0.f, lsum1 = 0.f;

    for (int kt = 0; kt < 32; kt++) {
        if (kt < 31) { load_kv(kt + 1, (kt + 1) & 1); CP_COMMIT(); CP_WAIT(1); }
        else         { CP_WAIT(0); }
        __syncthreads();

        const uint32_t st = sb + 32768 + (kt & 1) * ATT_STG;

        float S[8][4] = {};
#pragma unroll
        for (int ks = 0; ks < 4; ks++) {
            uint32_t qh[4], ql[4];
            uint32_t ao = SW((uint32_t)((wid * 16 + (lane & 15)) * 128
                             + ks * 32 + (lane >> 4) * 16));
            ldsm4(qh[0], qh[1], qh[2], qh[3], sb + ao);
            ldsm4(ql[0], ql[1], ql[2], ql[3], sb + 16384 + ao);
#pragma unroll
            for (int nf = 0; nf < 8; nf++) {
                uint32_t kh[2], kl[2];
                uint32_t bo = SW((uint32_t)((nf * 8 + (lane & 7)) * 128
                                 + ks * 32 + ((lane >> 3) & 1) * 16));
                ldsm2(kh[0], kh[1], st + bo);
                ldsm2(kl[0], kl[1], st + 8192 + bo);
                mma_bf16(S[nf], qh, kh);
                mma_bf16(S[nf], ql, kh);
                mma_bf16(S[nf], qh, kl);
            }
        }

        float mx0 = -1e30f, mx1 = -1e30f;
#pragma unroll
        for (int nf = 0; nf < 8; nf++) {
#pragma unroll
            for (int j = 0; j < 4; j++) S[nf][j] *= 0.125f;
            mx0 = fmaxf(mx0, fmaxf(S[nf][0], S[nf][1]));
            mx1 = fmaxf(mx1, fmaxf(S[nf][2], S[nf][3]));
        }
        mx0 = fmaxf(mx0, __shfl_xor_sync(0xffffffffu, mx0, 1));
        mx0 = fmaxf(mx0, __shfl_xor_sync(0xffffffffu, mx0, 2));
        mx1 = fmaxf(mx1, __shfl_xor_sync(0xffffffffu, mx1, 1));
        mx1 = fmaxf(mx1, __shfl_xor_sync(0xffffffffu, mx1, 2));
        float mn0 = fmaxf(mprev0, mx0), mn1 = fmaxf(mprev1, mx1);
        float fac0 = __expf(mprev0 - mn0), fac1 = __expf(mprev1 - mn1);
        mprev0 = mn0; mprev1 = mn1;

        uint32_t ph[8][2], pl[8][2];
        float ps0 = 0.f, ps1 = 0.f;
#pragma unroll
        for (int nf = 0; nf < 8; nf++) {
            float p00 = __expf(S[nf][0] - mn0), p01 = __expf(S[nf][1] - mn0);
            float p10 = __expf(S[nf][2] - mn1), p11 = __expf(S[nf][3] - mn1);
            ps0 += p00 + p01; ps1 += p10 + p11;
            ph[nf][0] = packbf(p00, p01);
            ph[nf][1] = packbf(p10, p11);
            pl[nf][0] = packbf(p00 - bfrt(p00), p01 - bfrt(p01));
            pl[nf][1] = packbf(p10 - bfrt(p10), p11 - bfrt(p11));
        }
        ps0 += __shfl_xor_sync(0xffffffffu, ps0, 1);
        ps0 += __shfl_xor_sync(0xffffffffu, ps0, 2);
        ps1 += __shfl_xor_sync(0xffffffffu, ps1, 1);
        ps1 += __shfl_xor_sync(0xffffffffu, ps1, 2);
        lsum0 = lsum0 * fac0 + ps0;
        lsum1 = lsum1 * fac1 + ps1;
#pragma unroll
        for (int nd = 0; nd < 8; nd++) {
            O[nd][0] *= fac0; O[nd][1] *= fac0;
            O[nd][2] *= fac1; O[nd][3] *= fac1;
        }

#pragma unroll
        for (int ks = 0; ks < 4; ks++) {
            uint32_t a_h[4] = { ph[2*ks][0], ph[2*ks][1], ph[2*ks+1][0], ph[2*ks+1][1] };
            uint32_t a_l[4] = { pl[2*ks][0], pl[2*ks][1], pl[2*ks+1][0], pl[2*ks+1][1] };
#pragma unroll
            for (int nd = 0; nd < 8; nd++) {
                uint32_t vh[2], vl[2];
                uint32_t vo = SW((uint32_t)((nd * 8 + (lane & 7)) * 128
                                 + ks * 32 + ((lane >> 3) & 1) * 16));
                ldsm2(vh[0], vh[1], st + 16384 + vo);
                ldsm2(vl[0], vl[1], st + 24576 + vo);
                mma_bf16(O[nd], a_h, vh);
                mma_bf16(O[nd], a_l, vh);
                mma_bf16(O[nd], a_h, vl);
            }
        }
        __syncthreads();
    }

    float inv0 = 1.f / lsum0, inv1 = 1.f / lsum1;
    float* Os = (float*)sm;
    {
        int r0 = wid * 16 + (lane >> 2);
#pragma unroll
        for (int nd = 0; nd < 8; nd++) {
            int cb = nd * 8 + (lane & 3) * 2;
            Os[r0 * 68 + cb]           = O[nd][0] * inv0;
            Os[r0 * 68 + cb + 1]       = O[nd][1] * inv0;
            Os[(r0 + 8) * 68 + cb]     = O[nd][2] * inv1;
            Os[(r0 + 8) * 68 + cb + 1] = O[nd][3] * inv1;
        }
    }
    __syncthreads();
#pragma unroll
    for (int j = 0; j < 8; j++) {
        int idx = tid + j * 256;
        int r = idx >> 4, c4 = (idx & 15) << 2;
        float4 v = *(float4*)(Os + r * 68 + c4);
        uint2 hh, ll;
        hh.x = packbf(v.x, v.y); hh.y = packbf(v.z, v.w);
        ll.x = packbf(v.x - bfrt(v.x), v.y - bfrt(v.y));
        ll.y = packbf(v.z - bfrt(v.z), v.w - bfrt(v.w));
        size_t off = ((size_t)b * SS + q0 + r) * DMODEL + h * DK + c4;
        *(uint2*)(g_CXh + off) = hh;
        *(uint2*)(g_CXl + off) = ll;
    }
}

// ---------------------------------------------------------------------------
extern "C" void kernel_launch(void* const* d_in, const int* in_sizes, int n_in,
                              void* d_out, int out_size)
{
    const float* query    = (const float*)d_in[0];
    const float* key_in   = (const float*)d_in[1];
    const float* value_in = (const float*)d_in[2];
    const float* Wq = (const float*)d_in[3];
    const float* bq = (const float*)d_in[4];
    const float* Wk = (const float*)d_in[5];
    const float* bk = (const float*)d_in[6];
    const float* Wv = (const float*)d_in[7];
    const float* bv = (const float*)d_in[8];
    const float* Wo = (const float*)d_in[9];
    const float* bo = (const float*)d_in[10];

    float* out  = (float*)d_out;
    float* outO = out;
    float* outK = out + (size_t)BB * SS * DMODEL;
    float* outV = outK + (size_t)BB * NKV * SS * DK;

    static cudaStream_t s1 = nullptr, s2 = nullptr;
    static cudaEvent_t evRoot, evW, evAW, e1, e2;
    static __nv_bfloat16 *Xh, *Xl, *Wh, *Wl, *CXh, *CXl;
    if (!s1) {
        cudaStreamCreateWithFlags(&s1, cudaStreamNonBlocking);
        cudaStreamCreateWithFlags(&s2, cudaStreamNonBlocking);
        cudaEventCreateWithFlags(&evRoot, cudaEventDisableTiming);
        cudaEventCreateWithFlags(&evW,    cudaEventDisableTiming);
        cudaEventCreateWithFlags(&evAW,   cudaEventDisableTiming);
        cudaEventCreateWithFlags(&e1,     cudaEventDisableTiming);
        cudaEventCreateWithFlags(&e2,     cudaEventDisableTiming);
        cudaGetSymbolAddress((void**)&Xh,  g_Xh);
        cudaGetSymbolAddress((void**)&Xl,  g_Xl);
        cudaGetSymbolAddress((void**)&Wh,  g_Wh);
        cudaGetSymbolAddress((void**)&Wl,  g_Wl);
        cudaGetSymbolAddress((void**)&CXh, g_CXh);
        cudaGetSymbolAddress((void**)&CXl, g_CXl);
        cudaFuncSetAttribute(gemm_mma, cudaFuncAttributeMaxDynamicSharedMemorySize, GEMM_SMEM);
        cudaFuncSetAttribute(attn_mma, cudaFuncAttributeMaxDynamicSharedMemorySize, ATT_SMEM);
    }

    const int M = BB * SS;

    cudaEventRecord(evRoot, 0);
    cudaStreamWaitEvent(s1, evRoot, 0);
    cudaStreamWaitEvent(s2, evRoot, 0);

    splitA_all<<<3 * XSLOT / 1024, 256>>>(query, key_in, value_in);
    splitW_all<<<dim3(80, 32), dim3(32, 8), 0, s1>>>(Wq, Wk, Wv, Wo);
    cudaEventRecord(evW, s1);
    cudaStreamWaitEvent(0, evW, 0);
    cudaEventRecord(evAW, 0);
    cudaStreamWaitEvent(s1, evAW, 0);
    cudaStreamWaitEvent(s2, evAW, 0);

    gemm_mma<<<dim3(16, M / 128), 256, GEMM_SMEM>>>(
        Xh, Xl, Wh, Wl, bq, out, 1);
    gemm_mma<<<dim3(4, M / 128), 256, GEMM_SMEM, s1>>>(
        Xh + XSLOT, Xl + XSLOT, Wh + WSLOT, Wl + WSLOT, bk, outK, 2);
    gemm_mma<<<dim3(4, M / 128), 256, GEMM_SMEM, s2>>>(
        Xh + 2 * XSLOT, Xl + 2 * XSLOT, Wh + 2 * WSLOT, Wl + 2 * WSLOT, bv, outV, 3);
    cudaEventRecord(e1, s1);
    cudaEventRecord(e2, s2);
    cudaStreamWaitEvent(0, e1, 0);
    cudaStreamWaitEvent(0, e2, 0);

    attn_mma<<<dim3(SS / 128, BB * NH), 256, ATT_SMEM>>>();

    gemm_mma<<<dim3(16, M / 128), 256, GEMM_SMEM>>>(
        CXh, CXl, Wh + 3 * WSLOT, Wl + 3 * WSLOT, bo, outO, 0);
}